// round 1
// baseline (speedup 1.0000x reference)
#include <cuda_runtime.h>
#include <cfloat>
#include <math.h>

// ---------------------------------------------------------------------------
// GMMNet forward: 4x GMMConv(mean agg, root weight) + residual + concat +
// segment_max pool + 2-layer MLP with eval-mode BN.
// ---------------------------------------------------------------------------

namespace {
constexpr int N_NODES = 50000;
constexpr int N_EDGES = 800000;
constexpr int H       = 64;
constexpr int KH      = 256;   // K * H
constexpr int G_GRAPHS = 50;
constexpr int NBLK_SCAN = (N_NODES + 255) / 256;   // 196
}

// -------------------- device scratch (static, no allocs) -------------------
__device__ float g_xg[(size_t)N_NODES * KH];     // 51.2 MB
__device__ float g_root[(size_t)N_NODES * H];
__device__ float g_gw[(size_t)N_EDGES * 4];
__device__ float g_x0[(size_t)N_NODES * H];
__device__ float g_x1[(size_t)N_NODES * H];
__device__ float g_x2[(size_t)N_NODES * H];
__device__ float g_x3[(size_t)N_NODES * H];
__device__ float g_x4[(size_t)N_NODES * H];
__device__ int   g_deg[N_NODES];
__device__ int   g_rowptr[N_NODES + 1];
__device__ int   g_cursor[N_NODES];
__device__ int2  g_col[N_EDGES];                 // (src, eid)
__device__ float g_invdeg[N_NODES];
__device__ int   g_part[256];
__device__ unsigned g_pmax[G_GRAPHS * 256];

// -------------------- helpers ----------------------------------------------
__device__ __forceinline__ unsigned fenc(float f) {
    unsigned u = __float_as_uint(f);
    return (u & 0x80000000u) ? ~u : (u | 0x80000000u);
}
__device__ __forceinline__ float fdec(unsigned u) {
    unsigned v = (u & 0x80000000u) ? (u ^ 0x80000000u) : ~u;
    return __uint_as_float(v);
}

// -------------------- CSR build --------------------------------------------
__global__ void k_zero_deg() {
    int i = blockIdx.x * blockDim.x + threadIdx.x;
    if (i < N_NODES) g_deg[i] = 0;
}

__global__ void k_hist(const int* __restrict__ ei) {
    int e = blockIdx.x * blockDim.x + threadIdx.x;
    if (e < N_EDGES) atomicAdd(&g_deg[ei[N_EDGES + e]], 1);
}

__global__ void k_scan_part() {
    __shared__ int s[256];
    int i = blockIdx.x * 256 + threadIdx.x;
    s[threadIdx.x] = (i < N_NODES) ? g_deg[i] : 0;
    __syncthreads();
    for (int o = 128; o > 0; o >>= 1) {
        if (threadIdx.x < o) s[threadIdx.x] += s[threadIdx.x + o];
        __syncthreads();
    }
    if (threadIdx.x == 0) g_part[blockIdx.x] = s[0];
}

__global__ void k_scan_total(int nblk) {
    __shared__ int s[256];
    int t = threadIdx.x;
    int orig = (t < nblk) ? g_part[t] : 0;
    s[t] = orig;
    __syncthreads();
    for (int o = 1; o < 256; o <<= 1) {
        int v = (t >= o) ? s[t - o] : 0;
        __syncthreads();
        s[t] += v;
        __syncthreads();
    }
    g_part[t] = s[t] - orig;   // exclusive scan of block sums
}

__global__ void k_scan_final() {
    __shared__ int s[256];
    int t = threadIdx.x;
    int i = blockIdx.x * 256 + t;
    int d = (i < N_NODES) ? g_deg[i] : 0;
    s[t] = d;
    __syncthreads();
    for (int o = 1; o < 256; o <<= 1) {
        int v = (t >= o) ? s[t - o] : 0;
        __syncthreads();
        s[t] += v;
        __syncthreads();
    }
    if (i < N_NODES) {
        int excl = g_part[blockIdx.x] + s[t] - d;
        g_rowptr[i] = excl;
        g_cursor[i] = excl;
        g_invdeg[i] = 1.0f / (float)max(d, 1);
    }
    if (i == 0) g_rowptr[N_NODES] = N_EDGES;
}

__global__ void k_scatter(const int* __restrict__ ei) {
    int e = blockIdx.x * blockDim.x + threadIdx.x;
    if (e < N_EDGES) {
        int srcn = ei[e];
        int dstn = ei[N_EDGES + e];
        int pos = atomicAdd(&g_cursor[dstn], 1);
        g_col[pos] = make_int2(srcn, e);
    }
}

// -------------------- Gaussian edge weights --------------------------------
__global__ void k_gw(const float* __restrict__ ea,
                     const float* __restrict__ mu,
                     const float* __restrict__ sig) {
    int e = blockIdx.x * blockDim.x + threadIdx.x;
    if (e >= N_EDGES) return;
    float e0 = ea[2 * e], e1 = ea[2 * e + 1];
#pragma unroll
    for (int k = 0; k < 4; k++) {
        float m0 = __ldg(mu + 2 * k), m1 = __ldg(mu + 2 * k + 1);
        float s0 = __ldg(sig + 2 * k), s1 = __ldg(sig + 2 * k + 1);
        float d0 = e0 - m0, d1 = e1 - m1;
        float t = d0 * d0 / (1e-15f + s0 * s0) + d1 * d1 / (1e-15f + s1 * s1);
        g_gw[4 * e + k] = expf(-0.5f * t);
    }
}

// -------------------- SGEMM: C[M,Nc] = A[M,64] @ B[64,Nc] (+bias) ----------
__global__ void k_gemm64(const float* __restrict__ A, const float* __restrict__ B,
                         const float* __restrict__ bias, float* __restrict__ C,
                         int M, int Nc) {
    __shared__ float sA[64 * 68];   // transposed: sA[k*68 + r]
    __shared__ float sB[64 * 68];   // sB[k*68 + c]
    const int bm = blockIdx.y * 64, bn = blockIdx.x * 64;
    const int tid = threadIdx.x;

#pragma unroll
    for (int i = 0; i < 4; i++) {
        int idx = tid + i * 256;       // 0..1023
        int r = idx >> 4, q = idx & 15;
        float4 va = make_float4(0.f, 0.f, 0.f, 0.f);
        if (bm + r < M)
            va = *reinterpret_cast<const float4*>(A + (size_t)(bm + r) * 64 + q * 4);
        sA[(q * 4 + 0) * 68 + r] = va.x;
        sA[(q * 4 + 1) * 68 + r] = va.y;
        sA[(q * 4 + 2) * 68 + r] = va.z;
        sA[(q * 4 + 3) * 68 + r] = va.w;
        float4 vb = *reinterpret_cast<const float4*>(B + (size_t)r * Nc + bn + q * 4);
        *reinterpret_cast<float4*>(&sB[r * 68 + q * 4]) = vb;
    }
    __syncthreads();

    const int tx = tid & 15, ty = tid >> 4;
    float acc[4][4];
#pragma unroll
    for (int i = 0; i < 4; i++)
#pragma unroll
        for (int j = 0; j < 4; j++) acc[i][j] = 0.f;

#pragma unroll 16
    for (int k = 0; k < 64; k++) {
        float4 a = *reinterpret_cast<const float4*>(&sA[k * 68 + ty * 4]);
        float4 b = *reinterpret_cast<const float4*>(&sB[k * 68 + tx * 4]);
        float av[4] = {a.x, a.y, a.z, a.w};
        float bv[4] = {b.x, b.y, b.z, b.w};
#pragma unroll
        for (int i = 0; i < 4; i++)
#pragma unroll
            for (int j = 0; j < 4; j++)
                acc[i][j] = fmaf(av[i], bv[j], acc[i][j]);
    }

    float4 bb = make_float4(0.f, 0.f, 0.f, 0.f);
    if (bias) bb = *reinterpret_cast<const float4*>(bias + bn + tx * 4);
#pragma unroll
    for (int i = 0; i < 4; i++) {
        int rr = bm + ty * 4 + i;
        if (rr < M) {
            float4 o;
            o.x = acc[i][0] + bb.x;
            o.y = acc[i][1] + bb.y;
            o.z = acc[i][2] + bb.z;
            o.w = acc[i][3] + bb.w;
            *reinterpret_cast<float4*>(C + (size_t)rr * Nc + bn + tx * 4) = o;
        }
    }
}

// -------------------- aggregation: warp per node ---------------------------
__global__ void k_agg(const float* __restrict__ root, float* __restrict__ out) {
    int w = (blockIdx.x * blockDim.x + threadIdx.x) >> 5;
    int lane = threadIdx.x & 31;
    if (w >= N_NODES) return;
    int s = g_rowptr[w], e = g_rowptr[w + 1];
    float a0 = 0.f, a1 = 0.f;
    for (int i = s; i < e; i++) {
        int2 se = g_col[i];
        float4 gw = *reinterpret_cast<const float4*>(&g_gw[(size_t)4 * se.y]);
        const float* p = g_xg + (size_t)se.x * KH + lane;
        a0 = fmaf(gw.x, p[0],   a0);
        a0 = fmaf(gw.y, p[64],  a0);
        a0 = fmaf(gw.z, p[128], a0);
        a0 = fmaf(gw.w, p[192], a0);
        a1 = fmaf(gw.x, p[32],  a1);
        a1 = fmaf(gw.y, p[96],  a1);
        a1 = fmaf(gw.z, p[160], a1);
        a1 = fmaf(gw.w, p[224], a1);
    }
    float inv = g_invdeg[w];
    float v0 = fmaf(a0, inv, root[(size_t)w * 64 + lane]);
    float v1 = fmaf(a1, inv, root[(size_t)w * 64 + lane + 32]);
    out[(size_t)w * 64 + lane]      = v0 > 0.f ? v0 : 0.01f * v0;
    out[(size_t)w * 64 + lane + 32] = v1 > 0.f ? v1 : 0.01f * v1;
}

// -------------------- x3 = x0 + x2 -----------------------------------------
__global__ void k_add() {
    int i = blockIdx.x * blockDim.x + threadIdx.x;
    if (i < N_NODES * H) g_x3[i] = g_x0[i] + g_x2[i];
}

// -------------------- pooling ----------------------------------------------
__global__ void k_zero_pmax() {
    int i = blockIdx.x * blockDim.x + threadIdx.x;
    if (i < G_GRAPHS * 256) g_pmax[i] = 0u;
}

__global__ void k_pool(const int* __restrict__ batch) {
    int f = threadIdx.x;                       // 0..255, feature in concat order
    int n0 = blockIdx.x * 64;
    int n1 = min(n0 + 64, N_NODES);
    const float* base = (f < 64) ? g_x4 : (f < 128) ? g_x1 : (f < 192) ? g_x2 : g_x3;
    int fo = f & 63;
    float m = -FLT_MAX;
    int cur = -1;
    for (int n = n0; n < n1; n++) {
        int b = batch[n];
        if (b != cur) {
            if (cur >= 0) atomicMax(&g_pmax[cur * 256 + f], fenc(m));
            cur = b;
            m = -FLT_MAX;
        }
        m = fmaxf(m, base[(size_t)n * 64 + fo]);
    }
    if (cur >= 0) atomicMax(&g_pmax[cur * 256 + f], fenc(m));
}

// -------------------- final MLP --------------------------------------------
__global__ void k_mlp(const float* __restrict__ w1, const float* __restrict__ b1,
                      const float* __restrict__ gamma, const float* __restrict__ beta,
                      const float* __restrict__ w2, const float* __restrict__ b2,
                      float* __restrict__ out) {
    int g = blockIdx.x;      // graph
    int t = threadIdx.x;     // 0..63
    __shared__ float sp[256];
    __shared__ float sz[64];
    for (int i = t; i < 256; i += 64) sp[i] = fdec(g_pmax[g * 256 + i]);
    __syncthreads();
    float acc = b1[t];
    for (int j = 0; j < 256; j++) acc = fmaf(sp[j], w1[j * 64 + t], acc);
    const float invs = 0.99999500003749969f;   // 1/sqrt(1 + 1e-5)
    acc = acc * invs * gamma[t] + beta[t];
    acc = fmaxf(acc, 0.f);
    sz[t] = acc;
    __syncthreads();
    if (t < 10) {
        float o = b2[t];
        for (int j = 0; j < 64; j++) o = fmaf(sz[j], w2[j * 10 + t], o);
        out[g * 10 + t] = o;
    }
}

// -------------------- host launch ------------------------------------------
extern "C" void kernel_launch(void* const* d_in, const int* in_sizes, int n_in,
                              void* d_out, int out_size) {
    (void)in_sizes; (void)n_in; (void)out_size;

    const float* x     = (const float*)d_in[0];
    const int*   ei    = (const int*)d_in[1];
    const int*   batch = (const int*)d_in[2];
    const float* ea    = (const float*)d_in[3];
    const float* g_w[4]   = {(const float*)d_in[4],  (const float*)d_in[9],
                             (const float*)d_in[14], (const float*)d_in[19]};
    const float* mu_w[4]  = {(const float*)d_in[5],  (const float*)d_in[10],
                             (const float*)d_in[15], (const float*)d_in[20]};
    const float* sig_w[4] = {(const float*)d_in[6],  (const float*)d_in[11],
                             (const float*)d_in[16], (const float*)d_in[21]};
    const float* rw_w[4]  = {(const float*)d_in[7],  (const float*)d_in[12],
                             (const float*)d_in[17], (const float*)d_in[22]};
    const float* b_w[4]   = {(const float*)d_in[8],  (const float*)d_in[13],
                             (const float*)d_in[18], (const float*)d_in[23]};
    const float* w1    = (const float*)d_in[24];
    const float* b1    = (const float*)d_in[25];
    const float* gamma = (const float*)d_in[26];
    const float* beta  = (const float*)d_in[27];
    const float* w2    = (const float*)d_in[28];
    const float* b2    = (const float*)d_in[29];

    float *p_xg, *p_root, *p_x0, *p_x1, *p_x2, *p_x3, *p_x4;
    cudaGetSymbolAddress((void**)&p_xg,   g_xg);
    cudaGetSymbolAddress((void**)&p_root, g_root);
    cudaGetSymbolAddress((void**)&p_x0,   g_x0);
    cudaGetSymbolAddress((void**)&p_x1,   g_x1);
    cudaGetSymbolAddress((void**)&p_x2,   g_x2);
    cudaGetSymbolAddress((void**)&p_x3,   g_x3);
    cudaGetSymbolAddress((void**)&p_x4,   g_x4);

    const int EB = (N_EDGES + 255) / 256;   // 3125

    // CSR build (deterministic work; slot order within a node is atomic-order)
    k_zero_deg<<<NBLK_SCAN, 256>>>();
    k_hist<<<EB, 256>>>(ei);
    k_scan_part<<<NBLK_SCAN, 256>>>();
    k_scan_total<<<1, 256>>>(NBLK_SCAN);
    k_scan_final<<<NBLK_SCAN, 256>>>();
    k_scatter<<<EB, 256>>>(ei);

    const dim3 gemm_xg_grid(4, (N_NODES + 63) / 64);     // Nc=256
    const dim3 gemm_rt_grid(1, (N_NODES + 63) / 64);     // Nc=64
    const int  agg_blocks = (N_NODES * 32 + 255) / 256;  // warp per node

    const float* layer_in[4]  = {x, p_x0, p_x1, p_x3};
    float*       layer_out[4] = {p_x0, p_x1, p_x2, p_x4};

    for (int l = 0; l < 4; l++) {
        if (l == 3)   // x3 = x0 + x2 before layer 3 consumes it
            k_add<<<(N_NODES * H + 255) / 256, 256>>>();
        k_gemm64<<<gemm_xg_grid, 256>>>(layer_in[l], g_w[l], nullptr, p_xg, N_NODES, 256);
        k_gemm64<<<gemm_rt_grid, 256>>>(layer_in[l], rw_w[l], b_w[l], p_root, N_NODES, 64);
        k_gw<<<EB, 256>>>(ea, mu_w[l], sig_w[l]);
        k_agg<<<agg_blocks, 256>>>(p_root, layer_out[l]);
    }

    k_zero_pmax<<<(G_GRAPHS * 256 + 255) / 256, 256>>>();
    k_pool<<<(N_NODES + 63) / 64, 256>>>(batch);
    k_mlp<<<G_GRAPHS, 64>>>(w1, b1, gamma, beta, w2, b2, (float*)d_out);
}

// round 2
// speedup vs baseline: 1.1585x; 1.1585x over previous
#include <cuda_runtime.h>
#include <cfloat>
#include <math.h>

// ---------------------------------------------------------------------------
// GMMNet forward, restructured: aggregate-then-transform.
//   Y[dst, k*64+f] = invdeg(dst) * sum_{e->dst} gw[e,k] * x_in[src,f]
//   Y[dst, 256+f]  = x_in[dst, f]                      (root path)
//   out = leakyrelu( Y @ B + b ),  B = [permuted g ; rw]  (Kdim=320)
// ---------------------------------------------------------------------------

namespace {
constexpr int N_NODES = 50000;
constexpr int N_EDGES = 800000;
constexpr int H       = 64;
constexpr int KY      = 320;   // 4*64 gaussian slices + 64 root slice
constexpr int G_GRAPHS = 50;
constexpr int NBLK_SCAN = (N_NODES + 255) / 256;   // 196
}

// -------------------- device scratch (static, no allocs) -------------------
__device__ float g_Y[(size_t)N_NODES * KY];      // 64 MB
__device__ float g_gw[(size_t)N_EDGES * 4];
__device__ float g_x0[(size_t)N_NODES * H];
__device__ float g_x1[(size_t)N_NODES * H];
__device__ float g_x2[(size_t)N_NODES * H];
__device__ float g_x3[(size_t)N_NODES * H];
__device__ float g_x4[(size_t)N_NODES * H];
__device__ int   g_deg[N_NODES];
__device__ int   g_rowptr[N_NODES + 1];
__device__ int   g_cursor[N_NODES];
__device__ int2  g_col[N_EDGES];                 // (src, eid)
__device__ float g_invdeg[N_NODES];
__device__ int   g_part[256];
__device__ unsigned g_pmax[G_GRAPHS * 256];

// -------------------- helpers ----------------------------------------------
__device__ __forceinline__ unsigned fenc(float f) {
    unsigned u = __float_as_uint(f);
    return (u & 0x80000000u) ? ~u : (u | 0x80000000u);
}
__device__ __forceinline__ float fdec(unsigned u) {
    unsigned v = (u & 0x80000000u) ? (u ^ 0x80000000u) : ~u;
    return __uint_as_float(v);
}

// -------------------- CSR build --------------------------------------------
__global__ void k_zero_deg() {
    int i = blockIdx.x * blockDim.x + threadIdx.x;
    if (i < N_NODES) g_deg[i] = 0;
}

__global__ void k_hist(const int* __restrict__ ei) {
    int e = blockIdx.x * blockDim.x + threadIdx.x;
    if (e < N_EDGES) atomicAdd(&g_deg[ei[N_EDGES + e]], 1);
}

__global__ void k_scan_part() {
    __shared__ int s[256];
    int i = blockIdx.x * 256 + threadIdx.x;
    s[threadIdx.x] = (i < N_NODES) ? g_deg[i] : 0;
    __syncthreads();
    for (int o = 128; o > 0; o >>= 1) {
        if (threadIdx.x < o) s[threadIdx.x] += s[threadIdx.x + o];
        __syncthreads();
    }
    if (threadIdx.x == 0) g_part[blockIdx.x] = s[0];
}

__global__ void k_scan_total(int nblk) {
    __shared__ int s[256];
    int t = threadIdx.x;
    int orig = (t < nblk) ? g_part[t] : 0;
    s[t] = orig;
    __syncthreads();
    for (int o = 1; o < 256; o <<= 1) {
        int v = (t >= o) ? s[t - o] : 0;
        __syncthreads();
        s[t] += v;
        __syncthreads();
    }
    g_part[t] = s[t] - orig;   // exclusive scan of block sums
}

__global__ void k_scan_final() {
    __shared__ int s[256];
    int t = threadIdx.x;
    int i = blockIdx.x * 256 + t;
    int d = (i < N_NODES) ? g_deg[i] : 0;
    s[t] = d;
    __syncthreads();
    for (int o = 1; o < 256; o <<= 1) {
        int v = (t >= o) ? s[t - o] : 0;
        __syncthreads();
        s[t] += v;
        __syncthreads();
    }
    if (i < N_NODES) {
        int excl = g_part[blockIdx.x] + s[t] - d;
        g_rowptr[i] = excl;
        g_cursor[i] = excl;
        g_invdeg[i] = 1.0f / (float)max(d, 1);
    }
    if (i == 0) g_rowptr[N_NODES] = N_EDGES;
}

__global__ void k_scatter(const int* __restrict__ ei) {
    int e = blockIdx.x * blockDim.x + threadIdx.x;
    if (e < N_EDGES) {
        int srcn = ei[e];
        int dstn = ei[N_EDGES + e];
        int pos = atomicAdd(&g_cursor[dstn], 1);
        g_col[pos] = make_int2(srcn, e);
    }
}

// -------------------- Gaussian edge weights --------------------------------
__global__ void k_gw(const float* __restrict__ ea,
                     const float* __restrict__ mu,
                     const float* __restrict__ sig) {
    int e = blockIdx.x * blockDim.x + threadIdx.x;
    if (e >= N_EDGES) return;
    float e0 = ea[2 * e], e1 = ea[2 * e + 1];
#pragma unroll
    for (int k = 0; k < 4; k++) {
        float m0 = __ldg(mu + 2 * k), m1 = __ldg(mu + 2 * k + 1);
        float s0 = __ldg(sig + 2 * k), s1 = __ldg(sig + 2 * k + 1);
        float d0 = e0 - m0, d1 = e1 - m1;
        float t = d0 * d0 / (1e-15f + s0 * s0) + d1 * d1 / (1e-15f + s1 * s1);
        g_gw[4 * e + k] = expf(-0.5f * t);
    }
}

// -------------------- aggregation into Y: warp per node --------------------
// Y[w, k*64 + f] = invdeg * sum_e gw[e,k] * xin[src, f]   (k<4)
// Y[w, 256 + f]  = xin[w, f]
__global__ void k_aggY(const float* __restrict__ xin) {
    int w = (blockIdx.x * blockDim.x + threadIdx.x) >> 5;
    int lane = threadIdx.x & 31;
    if (w >= N_NODES) return;
    int s = g_rowptr[w], e = g_rowptr[w + 1];
    float a[8];
#pragma unroll
    for (int i = 0; i < 8; i++) a[i] = 0.f;
    for (int i = s; i < e; i++) {
        int2 se = g_col[i];
        float4 gw = *reinterpret_cast<const float4*>(&g_gw[(size_t)4 * se.y]);
        const float* p = xin + (size_t)se.x * 64 + lane;
        float x0 = p[0], x1 = p[32];
        a[0] = fmaf(gw.x, x0, a[0]);  a[1] = fmaf(gw.x, x1, a[1]);
        a[2] = fmaf(gw.y, x0, a[2]);  a[3] = fmaf(gw.y, x1, a[3]);
        a[4] = fmaf(gw.z, x0, a[4]);  a[5] = fmaf(gw.z, x1, a[5]);
        a[6] = fmaf(gw.w, x0, a[6]);  a[7] = fmaf(gw.w, x1, a[7]);
    }
    float inv = g_invdeg[w];
    float* yo = g_Y + (size_t)w * KY;
#pragma unroll
    for (int k = 0; k < 4; k++) {
        yo[k * 64 + lane]      = a[2 * k]     * inv;
        yo[k * 64 + 32 + lane] = a[2 * k + 1] * inv;
    }
    yo[256 + lane]      = xin[(size_t)w * 64 + lane];
    yo[256 + 32 + lane] = xin[(size_t)w * 64 + 32 + lane];
}

// -------------------- fused GEMM: out = leakyrelu(Y @ B + b) ---------------
// B[j, h] = g[(j&63)*256 + (j>>6)*64 + h]  for j < 256   (permuted g)
//         = rw[(j-256)*64 + h]             for j >= 256  (root weight)
// M = N_NODES, N = 64, Kdim = 320 (5 chunks of 64)
__global__ void k_gemm320(const float* __restrict__ gW, const float* __restrict__ rw,
                          const float* __restrict__ bias, float* __restrict__ C) {
    __shared__ float sA[64 * 68];   // transposed: sA[k*68 + r]
    __shared__ float sB[64 * 68];   // sB[k*68 + c]
    const int bm = blockIdx.x * 64;
    const int tid = threadIdx.x;
    const int tx = tid & 15, ty = tid >> 4;

    float acc[4][4];
#pragma unroll
    for (int i = 0; i < 4; i++)
#pragma unroll
        for (int j = 0; j < 4; j++) acc[i][j] = 0.f;

    for (int kk = 0; kk < KY; kk += 64) {
        __syncthreads();
#pragma unroll
        for (int i = 0; i < 4; i++) {
            int idx = tid + i * 256;       // 0..1023
            int r = idx >> 4, q = idx & 15;
            // A tile: Y[bm+r, kk + q*4 .. +3]  -> transposed
            float4 va = make_float4(0.f, 0.f, 0.f, 0.f);
            if (bm + r < N_NODES)
                va = *reinterpret_cast<const float4*>(
                        g_Y + (size_t)(bm + r) * KY + kk + q * 4);
            sA[(q * 4 + 0) * 68 + r] = va.x;
            sA[(q * 4 + 1) * 68 + r] = va.y;
            sA[(q * 4 + 2) * 68 + r] = va.z;
            sA[(q * 4 + 3) * 68 + r] = va.w;
            // B tile: row j = kk + r (permuted source), cols q*4..+3
            int j = kk + r;
            const float* bp = (j < 256)
                ? gW + (size_t)(j & 63) * 256 + (j >> 6) * 64 + q * 4
                : rw + (size_t)(j - 256) * 64 + q * 4;
            *reinterpret_cast<float4*>(&sB[r * 68 + q * 4]) =
                *reinterpret_cast<const float4*>(bp);
        }
        __syncthreads();

#pragma unroll 16
        for (int k = 0; k < 64; k++) {
            float4 va = *reinterpret_cast<const float4*>(&sA[k * 68 + ty * 4]);
            float4 vb = *reinterpret_cast<const float4*>(&sB[k * 68 + tx * 4]);
            float av[4] = {va.x, va.y, va.z, va.w};
            float bv[4] = {vb.x, vb.y, vb.z, vb.w};
#pragma unroll
            for (int i = 0; i < 4; i++)
#pragma unroll
                for (int j = 0; j < 4; j++)
                    acc[i][j] = fmaf(av[i], bv[j], acc[i][j]);
        }
    }

    float4 bb = *reinterpret_cast<const float4*>(bias + tx * 4);
#pragma unroll
    for (int i = 0; i < 4; i++) {
        int rr = bm + ty * 4 + i;
        if (rr < N_NODES) {
            float v[4] = {acc[i][0] + bb.x, acc[i][1] + bb.y,
                          acc[i][2] + bb.z, acc[i][3] + bb.w};
            float4 o;
            o.x = v[0] > 0.f ? v[0] : 0.01f * v[0];
            o.y = v[1] > 0.f ? v[1] : 0.01f * v[1];
            o.z = v[2] > 0.f ? v[2] : 0.01f * v[2];
            o.w = v[3] > 0.f ? v[3] : 0.01f * v[3];
            *reinterpret_cast<float4*>(C + (size_t)rr * 64 + tx * 4) = o;
        }
    }
}

// -------------------- x3 = x0 + x2 -----------------------------------------
__global__ void k_add() {
    int i = blockIdx.x * blockDim.x + threadIdx.x;
    if (i < N_NODES * H) g_x3[i] = g_x0[i] + g_x2[i];
}

// -------------------- pooling ----------------------------------------------
__global__ void k_zero_pmax() {
    int i = blockIdx.x * blockDim.x + threadIdx.x;
    if (i < G_GRAPHS * 256) g_pmax[i] = 0u;
}

__global__ void k_pool(const int* __restrict__ batch) {
    int f = threadIdx.x;                       // 0..255, feature in concat order
    int n0 = blockIdx.x * 64;
    int n1 = min(n0 + 64, N_NODES);
    const float* base = (f < 64) ? g_x4 : (f < 128) ? g_x1 : (f < 192) ? g_x2 : g_x3;
    int fo = f & 63;
    float m = -FLT_MAX;
    int cur = -1;
    for (int n = n0; n < n1; n++) {
        int b = batch[n];
        if (b != cur) {
            if (cur >= 0) atomicMax(&g_pmax[cur * 256 + f], fenc(m));
            cur = b;
            m = -FLT_MAX;
        }
        m = fmaxf(m, base[(size_t)n * 64 + fo]);
    }
    if (cur >= 0) atomicMax(&g_pmax[cur * 256 + f], fenc(m));
}

// -------------------- final MLP --------------------------------------------
__global__ void k_mlp(const float* __restrict__ w1, const float* __restrict__ b1,
                      const float* __restrict__ gamma, const float* __restrict__ beta,
                      const float* __restrict__ w2, const float* __restrict__ b2,
                      float* __restrict__ out) {
    int g = blockIdx.x;      // graph
    int t = threadIdx.x;     // 0..63
    __shared__ float sp[256];
    __shared__ float sz[64];
    for (int i = t; i < 256; i += 64) sp[i] = fdec(g_pmax[g * 256 + i]);
    __syncthreads();
    float acc = b1[t];
    for (int j = 0; j < 256; j++) acc = fmaf(sp[j], w1[j * 64 + t], acc);
    const float invs = 0.99999500003749969f;   // 1/sqrt(1 + 1e-5)
    acc = acc * invs * gamma[t] + beta[t];
    acc = fmaxf(acc, 0.f);
    sz[t] = acc;
    __syncthreads();
    if (t < 10) {
        float o = b2[t];
        for (int j = 0; j < 64; j++) o = fmaf(sz[j], w2[j * 10 + t], o);
        out[g * 10 + t] = o;
    }
}

// -------------------- host launch ------------------------------------------
extern "C" void kernel_launch(void* const* d_in, const int* in_sizes, int n_in,
                              void* d_out, int out_size) {
    (void)in_sizes; (void)n_in; (void)out_size;

    const float* x     = (const float*)d_in[0];
    const int*   ei    = (const int*)d_in[1];
    const int*   batch = (const int*)d_in[2];
    const float* ea    = (const float*)d_in[3];
    const float* g_w[4]   = {(const float*)d_in[4],  (const float*)d_in[9],
                             (const float*)d_in[14], (const float*)d_in[19]};
    const float* mu_w[4]  = {(const float*)d_in[5],  (const float*)d_in[10],
                             (const float*)d_in[15], (const float*)d_in[20]};
    const float* sig_w[4] = {(const float*)d_in[6],  (const float*)d_in[11],
                             (const float*)d_in[16], (const float*)d_in[21]};
    const float* rw_w[4]  = {(const float*)d_in[7],  (const float*)d_in[12],
                             (const float*)d_in[17], (const float*)d_in[22]};
    const float* b_w[4]   = {(const float*)d_in[8],  (const float*)d_in[13],
                             (const float*)d_in[18], (const float*)d_in[23]};
    const float* w1    = (const float*)d_in[24];
    const float* b1    = (const float*)d_in[25];
    const float* gamma = (const float*)d_in[26];
    const float* beta  = (const float*)d_in[27];
    const float* w2    = (const float*)d_in[28];
    const float* b2    = (const float*)d_in[29];

    float *p_x0, *p_x1, *p_x2, *p_x3, *p_x4;
    cudaGetSymbolAddress((void**)&p_x0, g_x0);
    cudaGetSymbolAddress((void**)&p_x1, g_x1);
    cudaGetSymbolAddress((void**)&p_x2, g_x2);
    cudaGetSymbolAddress((void**)&p_x3, g_x3);
    cudaGetSymbolAddress((void**)&p_x4, g_x4);

    const int EB = (N_EDGES + 255) / 256;   // 3125

    // CSR build
    k_zero_deg<<<NBLK_SCAN, 256>>>();
    k_hist<<<EB, 256>>>(ei);
    k_scan_part<<<NBLK_SCAN, 256>>>();
    k_scan_total<<<1, 256>>>(NBLK_SCAN);
    k_scan_final<<<NBLK_SCAN, 256>>>();
    k_scatter<<<EB, 256>>>(ei);

    const int  agg_blocks  = (N_NODES * 32 + 255) / 256;   // warp per node
    const int  gemm_blocks = (N_NODES + 63) / 64;          // 782

    const float* layer_in[4]  = {x, p_x0, p_x1, p_x3};
    float*       layer_out[4] = {p_x0, p_x1, p_x2, p_x4};

    for (int l = 0; l < 4; l++) {
        if (l == 3)   // x3 = x0 + x2 before layer 3 consumes it
            k_add<<<(N_NODES * H + 255) / 256, 256>>>();
        k_gw<<<EB, 256>>>(ea, mu_w[l], sig_w[l]);
        k_aggY<<<agg_blocks, 256>>>(layer_in[l]);
        k_gemm320<<<gemm_blocks, 256>>>(g_w[l], rw_w[l], b_w[l], layer_out[l]);
    }

    k_zero_pmax<<<(G_GRAPHS * 256 + 255) / 256, 256>>>();
    k_pool<<<(N_NODES + 63) / 64, 256>>>(batch);
    k_mlp<<<G_GRAPHS, 64>>>(w1, b1, gamma, beta, w2, b2, (float*)d_out);
}

// round 3
// speedup vs baseline: 1.4455x; 1.2478x over previous
#include <cuda_runtime.h>
#include <cuda_bf16.h>
#include <cfloat>
#include <math.h>

// ---------------------------------------------------------------------------
// GMMNet forward: aggregate-then-transform + bf16 split tensor-core GEMM.
//   Y[dst, k*64+f] = invdeg(dst) * sum_{e->dst} gw[e,k] * x_in[src,f]
//   Y[dst, 256+f]  = x_in[dst, f]                      (root path)
//   out = leakyrelu( Y @ B + b ),  B = [permuted g ; rw]  (Kdim=320)
// Y and B stored as bf16 hi/lo pairs; GEMM = Ah*Bh + Ah*Bl + Al*Bh (mma.sync).
// ---------------------------------------------------------------------------

namespace {
constexpr int N_NODES = 50000;
constexpr int N_EDGES = 800000;
constexpr int H       = 64;
constexpr int KY      = 320;
constexpr int G_GRAPHS = 50;
constexpr int NBLK_SCAN = (N_NODES + 255) / 256;   // 196
}

// -------------------- device scratch (static, no allocs) -------------------
__device__ __nv_bfloat16 g_Yh[(size_t)N_NODES * KY];   // 32 MB
__device__ __nv_bfloat16 g_Yl[(size_t)N_NODES * KY];   // 32 MB
__device__ __nv_bfloat16 g_Bh[4 * KY * H];
__device__ __nv_bfloat16 g_Bl[4 * KY * H];
__device__ float g_gw[(size_t)N_EDGES * 4];
__device__ float g_x0[(size_t)N_NODES * H];
__device__ float g_x1[(size_t)N_NODES * H];
__device__ float g_x2[(size_t)N_NODES * H];
__device__ float g_x3[(size_t)N_NODES * H];
__device__ float g_x4[(size_t)N_NODES * H];
__device__ int   g_deg[N_NODES];
__device__ int   g_rowptr[N_NODES + 1];
__device__ int   g_cursor[N_NODES];
__device__ int2  g_col[N_EDGES];                 // (src, eid)
__device__ float g_invdeg[N_NODES];
__device__ int   g_part[256];
__device__ unsigned g_pmax[G_GRAPHS * 256];

// -------------------- helpers ----------------------------------------------
__device__ __forceinline__ unsigned fenc(float f) {
    unsigned u = __float_as_uint(f);
    return (u & 0x80000000u) ? ~u : (u | 0x80000000u);
}
__device__ __forceinline__ float fdec(unsigned u) {
    unsigned v = (u & 0x80000000u) ? (u ^ 0x80000000u) : ~u;
    return __uint_as_float(v);
}
__device__ __forceinline__ void store_split(__nv_bfloat16* yh, __nv_bfloat16* yl,
                                            int i, float v) {
    __nv_bfloat16 h = __float2bfloat16_rn(v);
    yh[i] = h;
    yl[i] = __float2bfloat16_rn(v - __bfloat162float(h));
}
__device__ __forceinline__ void mma_bf16(float* d, const unsigned* a, const unsigned* b) {
    asm volatile(
        "mma.sync.aligned.m16n8k16.row.col.f32.bf16.bf16.f32 "
        "{%0,%1,%2,%3}, {%4,%5,%6,%7}, {%8,%9}, {%0,%1,%2,%3};\n"
        : "+f"(d[0]), "+f"(d[1]), "+f"(d[2]), "+f"(d[3])
        : "r"(a[0]), "r"(a[1]), "r"(a[2]), "r"(a[3]),
          "r"(b[0]), "r"(b[1]));
}

// -------------------- CSR build --------------------------------------------
__global__ void k_zero_deg() {
    int i = blockIdx.x * blockDim.x + threadIdx.x;
    if (i < N_NODES) g_deg[i] = 0;
}

__global__ void k_hist(const int* __restrict__ ei) {
    int e = blockIdx.x * blockDim.x + threadIdx.x;
    if (e < N_EDGES) atomicAdd(&g_deg[ei[N_EDGES + e]], 1);
}

__global__ void k_scan_part() {
    __shared__ int s[256];
    int i = blockIdx.x * 256 + threadIdx.x;
    s[threadIdx.x] = (i < N_NODES) ? g_deg[i] : 0;
    __syncthreads();
    for (int o = 128; o > 0; o >>= 1) {
        if (threadIdx.x < o) s[threadIdx.x] += s[threadIdx.x + o];
        __syncthreads();
    }
    if (threadIdx.x == 0) g_part[blockIdx.x] = s[0];
}

__global__ void k_scan_total(int nblk) {
    __shared__ int s[256];
    int t = threadIdx.x;
    int orig = (t < nblk) ? g_part[t] : 0;
    s[t] = orig;
    __syncthreads();
    for (int o = 1; o < 256; o <<= 1) {
        int v = (t >= o) ? s[t - o] : 0;
        __syncthreads();
        s[t] += v;
        __syncthreads();
    }
    g_part[t] = s[t] - orig;
}

__global__ void k_scan_final() {
    __shared__ int s[256];
    int t = threadIdx.x;
    int i = blockIdx.x * 256 + t;
    int d = (i < N_NODES) ? g_deg[i] : 0;
    s[t] = d;
    __syncthreads();
    for (int o = 1; o < 256; o <<= 1) {
        int v = (t >= o) ? s[t - o] : 0;
        __syncthreads();
        s[t] += v;
        __syncthreads();
    }
    if (i < N_NODES) {
        int excl = g_part[blockIdx.x] + s[t] - d;
        g_rowptr[i] = excl;
        g_cursor[i] = excl;
        g_invdeg[i] = 1.0f / (float)max(d, 1);
    }
    if (i == 0) g_rowptr[N_NODES] = N_EDGES;
}

__global__ void k_scatter(const int* __restrict__ ei) {
    int e = blockIdx.x * blockDim.x + threadIdx.x;
    if (e < N_EDGES) {
        int srcn = ei[e];
        int dstn = ei[N_EDGES + e];
        int pos = atomicAdd(&g_cursor[dstn], 1);
        g_col[pos] = make_int2(srcn, e);
    }
}

// -------------------- weight split setup -----------------------------------
// B[l][j][h]: j<256 -> g_l[(j&63)*256 + (j>>6)*64 + h]; else rw_l[(j-256)*64+h]
__global__ void k_splitB(const float* g0, const float* r0,
                         const float* g1, const float* r1,
                         const float* g2, const float* r2,
                         const float* g3, const float* r3) {
    int idx = blockIdx.x * blockDim.x + threadIdx.x;
    if (idx >= 4 * KY * H) return;
    int l = idx / (KY * H);
    int rem = idx % (KY * H);
    int j = rem / H, h = rem % H;
    const float* gW = (l == 0) ? g0 : (l == 1) ? g1 : (l == 2) ? g2 : g3;
    const float* rw = (l == 0) ? r0 : (l == 1) ? r1 : (l == 2) ? r2 : r3;
    float v = (j < 256) ? gW[(size_t)(j & 63) * 256 + (j >> 6) * 64 + h]
                        : rw[(size_t)(j - 256) * 64 + h];
    store_split(g_Bh, g_Bl, idx, v);
}

// -------------------- Gaussian edge weights --------------------------------
__global__ void k_gw(const float* __restrict__ ea,
                     const float* __restrict__ mu,
                     const float* __restrict__ sig) {
    int e = blockIdx.x * blockDim.x + threadIdx.x;
    if (e >= N_EDGES) return;
    float e0 = ea[2 * e], e1 = ea[2 * e + 1];
#pragma unroll
    for (int k = 0; k < 4; k++) {
        float m0 = __ldg(mu + 2 * k), m1 = __ldg(mu + 2 * k + 1);
        float s0 = __ldg(sig + 2 * k), s1 = __ldg(sig + 2 * k + 1);
        float d0 = e0 - m0, d1 = e1 - m1;
        float t = d0 * d0 / (1e-15f + s0 * s0) + d1 * d1 / (1e-15f + s1 * s1);
        g_gw[4 * e + k] = expf(-0.5f * t);
    }
}

// -------------------- aggregation into Yh/Yl: warp per node ----------------
__global__ void k_aggY(const float* __restrict__ xin) {
    int w = (blockIdx.x * blockDim.x + threadIdx.x) >> 5;
    int lane = threadIdx.x & 31;
    if (w >= N_NODES) return;
    int s = g_rowptr[w], e = g_rowptr[w + 1];
    float a[8];
#pragma unroll
    for (int i = 0; i < 8; i++) a[i] = 0.f;
    for (int i = s; i < e; i++) {
        int2 se = g_col[i];
        float4 gw = *reinterpret_cast<const float4*>(&g_gw[(size_t)4 * se.y]);
        const float* p = xin + (size_t)se.x * 64 + lane;
        float x0 = p[0], x1 = p[32];
        a[0] = fmaf(gw.x, x0, a[0]);  a[1] = fmaf(gw.x, x1, a[1]);
        a[2] = fmaf(gw.y, x0, a[2]);  a[3] = fmaf(gw.y, x1, a[3]);
        a[4] = fmaf(gw.z, x0, a[4]);  a[5] = fmaf(gw.z, x1, a[5]);
        a[6] = fmaf(gw.w, x0, a[6]);  a[7] = fmaf(gw.w, x1, a[7]);
    }
    float inv = g_invdeg[w];
    __nv_bfloat16* yh = g_Yh + (size_t)w * KY;
    __nv_bfloat16* yl = g_Yl + (size_t)w * KY;
#pragma unroll
    for (int k = 0; k < 4; k++) {
        store_split(yh, yl, k * 64 + lane,      a[2 * k]     * inv);
        store_split(yh, yl, k * 64 + 32 + lane, a[2 * k + 1] * inv);
    }
    store_split(yh, yl, 256 + lane,      xin[(size_t)w * 64 + lane]);
    store_split(yh, yl, 256 + 32 + lane, xin[(size_t)w * 64 + 32 + lane]);
}

// -------------------- tensor-core GEMM: out = lrelu(Y @ B + bias) ----------
// Block tile: M=128, N=64, K streamed in chunks of 32 (10 chunks).
// 8 warps: warp (w&3) -> m 32-strip, (w>>2) -> n 32-strip.
__global__ __launch_bounds__(256) void k_gemm_mma(int layer,
                                                  const float* __restrict__ bias,
                                                  float* __restrict__ C) {
    __shared__ unsigned short sAh[128][40];
    __shared__ unsigned short sAl[128][40];
    __shared__ unsigned short sBh[64][40];   // transposed: [n][k_local]
    __shared__ unsigned short sBl[64][40];
    __shared__ float sBias[64];

    const int tid = threadIdx.x;
    const int bm = blockIdx.x * 128;
    if (tid < 64) sBias[tid] = bias[tid];

    const int w = tid >> 5, lane = tid & 31;
    const int wm = (w & 3) * 32, wn = (w >> 2) * 32;
    const int g = lane >> 2, tig = lane & 3;

    const __nv_bfloat16* Bh = g_Bh + (size_t)layer * KY * H;
    const __nv_bfloat16* Bl = g_Bl + (size_t)layer * KY * H;

    float acc[2][4][4];
#pragma unroll
    for (int mt = 0; mt < 2; mt++)
#pragma unroll
        for (int nt = 0; nt < 4; nt++)
#pragma unroll
            for (int i = 0; i < 4; i++) acc[mt][nt][i] = 0.f;

    for (int c = 0; c < 10; c++) {
        int k0 = c * 32;
        __syncthreads();
        // A chunk: 128 rows x 32 u16 -> uint4 (8 u16) x 512 -> 2 per thread
#pragma unroll
        for (int i = 0; i < 2; i++) {
            int idx = tid + i * 256;
            int r = idx >> 2, q = idx & 3;
            uint4 vh = make_uint4(0, 0, 0, 0), vl = make_uint4(0, 0, 0, 0);
            if (bm + r < N_NODES) {
                vh = *reinterpret_cast<const uint4*>(
                        g_Yh + (size_t)(bm + r) * KY + k0 + q * 8);
                vl = *reinterpret_cast<const uint4*>(
                        g_Yl + (size_t)(bm + r) * KY + k0 + q * 8);
            }
            *reinterpret_cast<uint4*>(&sAh[r][q * 8]) = vh;
            *reinterpret_cast<uint4*>(&sAl[r][q * 8]) = vl;
        }
        // B chunk: [k0..k0+31][64] row-major source -> transposed smem [h][kl]
#pragma unroll
        for (int i = 0; i < 8; i++) {
            int idx = tid + i * 256;   // 0..2047
            int kl = idx >> 6, h = idx & 63;
            sBh[h][kl] = reinterpret_cast<const unsigned short*>(Bh)[(k0 + kl) * 64 + h];
            sBl[h][kl] = reinterpret_cast<const unsigned short*>(Bl)[(k0 + kl) * 64 + h];
        }
        __syncthreads();

#pragma unroll
        for (int ks = 0; ks < 2; ks++) {
            int kl0 = ks * 16;
            unsigned ah[2][4], al[2][4], bh[4][2], bl[4][2];
#pragma unroll
            for (int mt = 0; mt < 2; mt++) {
                int rm = wm + mt * 16;
                ah[mt][0] = *reinterpret_cast<const unsigned*>(&sAh[rm + g][kl0 + tig * 2]);
                ah[mt][1] = *reinterpret_cast<const unsigned*>(&sAh[rm + g + 8][kl0 + tig * 2]);
                ah[mt][2] = *reinterpret_cast<const unsigned*>(&sAh[rm + g][kl0 + tig * 2 + 8]);
                ah[mt][3] = *reinterpret_cast<const unsigned*>(&sAh[rm + g + 8][kl0 + tig * 2 + 8]);
                al[mt][0] = *reinterpret_cast<const unsigned*>(&sAl[rm + g][kl0 + tig * 2]);
                al[mt][1] = *reinterpret_cast<const unsigned*>(&sAl[rm + g + 8][kl0 + tig * 2]);
                al[mt][2] = *reinterpret_cast<const unsigned*>(&sAl[rm + g][kl0 + tig * 2 + 8]);
                al[mt][3] = *reinterpret_cast<const unsigned*>(&sAl[rm + g + 8][kl0 + tig * 2 + 8]);
            }
#pragma unroll
            for (int nt = 0; nt < 4; nt++) {
                int nn = wn + nt * 8 + g;
                bh[nt][0] = *reinterpret_cast<const unsigned*>(&sBh[nn][kl0 + tig * 2]);
                bh[nt][1] = *reinterpret_cast<const unsigned*>(&sBh[nn][kl0 + tig * 2 + 8]);
                bl[nt][0] = *reinterpret_cast<const unsigned*>(&sBl[nn][kl0 + tig * 2]);
                bl[nt][1] = *reinterpret_cast<const unsigned*>(&sBl[nn][kl0 + tig * 2 + 8]);
            }
#pragma unroll
            for (int mt = 0; mt < 2; mt++)
#pragma unroll
                for (int nt = 0; nt < 4; nt++) {
                    mma_bf16(acc[mt][nt], ah[mt], bh[nt]);
                    mma_bf16(acc[mt][nt], ah[mt], bl[nt]);
                    mma_bf16(acc[mt][nt], al[mt], bh[nt]);
                }
        }
    }

    // epilogue: bias + leakyrelu, float2 stores
#pragma unroll
    for (int mt = 0; mt < 2; mt++) {
        int r0 = bm + wm + mt * 16 + g;
        int r1 = r0 + 8;
#pragma unroll
        for (int nt = 0; nt < 4; nt++) {
            int col = wn + nt * 8 + tig * 2;
            float b0 = sBias[col], b1 = sBias[col + 1];
            if (r0 < N_NODES) {
                float v0 = acc[mt][nt][0] + b0;
                float v1 = acc[mt][nt][1] + b1;
                float2 o;
                o.x = v0 > 0.f ? v0 : 0.01f * v0;
                o.y = v1 > 0.f ? v1 : 0.01f * v1;
                *reinterpret_cast<float2*>(C + (size_t)r0 * 64 + col) = o;
            }
            if (r1 < N_NODES) {
                float v0 = acc[mt][nt][2] + b0;
                float v1 = acc[mt][nt][3] + b1;
                float2 o;
                o.x = v0 > 0.f ? v0 : 0.01f * v0;
                o.y = v1 > 0.f ? v1 : 0.01f * v1;
                *reinterpret_cast<float2*>(C + (size_t)r1 * 64 + col) = o;
            }
        }
    }
}

// -------------------- x3 = x0 + x2 -----------------------------------------
__global__ void k_add() {
    int i = blockIdx.x * blockDim.x + threadIdx.x;
    if (i < N_NODES * H) g_x3[i] = g_x0[i] + g_x2[i];
}

// -------------------- pooling ----------------------------------------------
__global__ void k_zero_pmax() {
    int i = blockIdx.x * blockDim.x + threadIdx.x;
    if (i < G_GRAPHS * 256) g_pmax[i] = 0u;
}

__global__ void k_pool(const int* __restrict__ batch) {
    int f = threadIdx.x;
    int n0 = blockIdx.x * 64;
    int n1 = min(n0 + 64, N_NODES);
    const float* base = (f < 64) ? g_x4 : (f < 128) ? g_x1 : (f < 192) ? g_x2 : g_x3;
    int fo = f & 63;
    float m = -FLT_MAX;
    int cur = -1;
    for (int n = n0; n < n1; n++) {
        int b = batch[n];
        if (b != cur) {
            if (cur >= 0) atomicMax(&g_pmax[cur * 256 + f], fenc(m));
            cur = b;
            m = -FLT_MAX;
        }
        m = fmaxf(m, base[(size_t)n * 64 + fo]);
    }
    if (cur >= 0) atomicMax(&g_pmax[cur * 256 + f], fenc(m));
}

// -------------------- final MLP --------------------------------------------
__global__ void k_mlp(const float* __restrict__ w1, const float* __restrict__ b1,
                      const float* __restrict__ gamma, const float* __restrict__ beta,
                      const float* __restrict__ w2, const float* __restrict__ b2,
                      float* __restrict__ out) {
    int g = blockIdx.x;
    int t = threadIdx.x;
    __shared__ float sp[256];
    __shared__ float sz[64];
    for (int i = t; i < 256; i += 64) sp[i] = fdec(g_pmax[g * 256 + i]);
    __syncthreads();
    float acc = b1[t];
    for (int j = 0; j < 256; j++) acc = fmaf(sp[j], w1[j * 64 + t], acc);
    const float invs = 0.99999500003749969f;   // 1/sqrt(1 + 1e-5)
    acc = acc * invs * gamma[t] + beta[t];
    acc = fmaxf(acc, 0.f);
    sz[t] = acc;
    __syncthreads();
    if (t < 10) {
        float o = b2[t];
        for (int j = 0; j < 64; j++) o = fmaf(sz[j], w2[j * 10 + t], o);
        out[g * 10 + t] = o;
    }
}

// -------------------- host launch ------------------------------------------
extern "C" void kernel_launch(void* const* d_in, const int* in_sizes, int n_in,
                              void* d_out, int out_size) {
    (void)in_sizes; (void)n_in; (void)out_size;

    const float* x     = (const float*)d_in[0];
    const int*   ei    = (const int*)d_in[1];
    const int*   batch = (const int*)d_in[2];
    const float* ea    = (const float*)d_in[3];
    const float* g_w[4]   = {(const float*)d_in[4],  (const float*)d_in[9],
                             (const float*)d_in[14], (const float*)d_in[19]};
    const float* mu_w[4]  = {(const float*)d_in[5],  (const float*)d_in[10],
                             (const float*)d_in[15], (const float*)d_in[20]};
    const float* sig_w[4] = {(const float*)d_in[6],  (const float*)d_in[11],
                             (const float*)d_in[16], (const float*)d_in[21]};
    const float* rw_w[4]  = {(const float*)d_in[7],  (const float*)d_in[12],
                             (const float*)d_in[17], (const float*)d_in[22]};
    const float* b_w[4]   = {(const float*)d_in[8],  (const float*)d_in[13],
                             (const float*)d_in[18], (const float*)d_in[23]};
    const float* w1    = (const float*)d_in[24];
    const float* b1    = (const float*)d_in[25];
    const float* gamma = (const float*)d_in[26];
    const float* beta  = (const float*)d_in[27];
    const float* w2    = (const float*)d_in[28];
    const float* b2    = (const float*)d_in[29];

    float *p_x0, *p_x1, *p_x2, *p_x3, *p_x4;
    cudaGetSymbolAddress((void**)&p_x0, g_x0);
    cudaGetSymbolAddress((void**)&p_x1, g_x1);
    cudaGetSymbolAddress((void**)&p_x2, g_x2);
    cudaGetSymbolAddress((void**)&p_x3, g_x3);
    cudaGetSymbolAddress((void**)&p_x4, g_x4);

    const int EB = (N_EDGES + 255) / 256;   // 3125

    // CSR build + weight split
    k_zero_deg<<<NBLK_SCAN, 256>>>();
    k_hist<<<EB, 256>>>(ei);
    k_scan_part<<<NBLK_SCAN, 256>>>();
    k_scan_total<<<1, 256>>>(NBLK_SCAN);
    k_scan_final<<<NBLK_SCAN, 256>>>();
    k_scatter<<<EB, 256>>>(ei);
    k_splitB<<<(4 * KY * H + 255) / 256, 256>>>(g_w[0], rw_w[0], g_w[1], rw_w[1],
                                                g_w[2], rw_w[2], g_w[3], rw_w[3]);

    const int agg_blocks  = (N_NODES * 32 + 255) / 256;
    const int gemm_blocks = (N_NODES + 127) / 128;   // 391

    const float* layer_in[4]  = {x, p_x0, p_x1, p_x3};
    float*       layer_out[4] = {p_x0, p_x1, p_x2, p_x4};

    for (int l = 0; l < 4; l++) {
        if (l == 3)
            k_add<<<(N_NODES * H + 255) / 256, 256>>>();
        k_gw<<<EB, 256>>>(ea, mu_w[l], sig_w[l]);
        k_aggY<<<agg_blocks, 256>>>(layer_in[l]);
        k_gemm_mma<<<gemm_blocks, 256>>>(l, b_w[l], layer_out[l]);
    }

    k_zero_pmax<<<(G_GRAPHS * 256 + 255) / 256, 256>>>();
    k_pool<<<(N_NODES + 63) / 64, 256>>>(batch);
    k_mlp<<<G_GRAPHS, 64>>>(w1, b1, gamma, beta, w2, b2, (float*)d_out);
}